// round 13
// baseline (speedup 1.0000x reference)
#include <cuda_runtime.h>
#include <cstdint>

// Problem constants (fixed by the reference setup)
#define NB 65536        // batch rows
#define NF 512          // in_features
#define NK 1299         // number of centers
#define THREADS 256
#define WPB 8                       // warps per block
#define GRID 608                    // 152 SMs * 4 blocks (fits: ~40 regs, 32 warps/SM)

// Fixed-point loss accumulator: integer adds commute exactly -> deterministic.
#define LOSS_SCALE 1073741824.0f    // 2^30
__device__ unsigned long long g_loss_acc;   // zero-init; last block resets
__device__ unsigned int      g_arrive;      // zero-init; last block resets

// Persistent kernel: each warp grid-strides over rows (chip-wide contiguous
// span per iteration -> sequential DRAM streaming, same as the frozen loop).
// The ONLY cross-block sync is one acq_rel arrival per block at its tail —
// when co-resident blocks are also done streaming, so the acquire's L1
// invalidation destroys nothing. Non-last blocks exit; no spin, no deadlock.
__global__ __launch_bounds__(THREADS)
void predict_persist(const float* __restrict__ input,
                     const float* __restrict__ factor,
                     const int* __restrict__ label,     // JAX downcasts int64->int32
                     const float* __restrict__ centers,
                     float* __restrict__ out)           // out[0]=loss, out[1..NB]=pred
{
    const int warp = threadIdx.x >> 5;
    const int lane = threadIdx.x & 31;
    const int totalWarps = GRID * WPB;                  // 4864

    float lloss = 0.0f;   // meaningful in lane 0 only; fixed order -> deterministic

    for (int b = blockIdx.x * WPB + warp; b < NB; b += totalWarps) {
        const float4* in4 = reinterpret_cast<const float4*>(input + (size_t)b * NF);
        int c = label[b];
        c = (c < 0) ? 0 : (c >= NK ? NK - 1 : c);       // in-bounds insurance
        const float4* ce4 = reinterpret_cast<const float4*>(centers + (size_t)c * NF);

        // input: zero reuse -> bypass L1 (__ldcg); centers: default (L1-cached).
        float acc = 0.0f;
#pragma unroll
        for (int i = 0; i < 4; i++) {
            float4 a = __ldcg(&in4[lane + 32 * i]);
            float4 w = ce4[lane + 32 * i];
            acc += a.x * w.x + a.y * w.y + a.z * w.z + a.w * w.w;
        }
#pragma unroll
        for (int o = 16; o; o >>= 1)
            acc += __shfl_xor_sync(0xffffffffu, acc, o);

        if (lane == 0) {
            float p = 12.0f * tanhf(acc);
            __stcg(&out[1 + b], p);                     // streamed output, skip L1
            float d = p - factor[b];
            float ad = fabsf(d);
            lloss += (ad < 1.0f) ? 0.5f * d * d : (ad - 0.5f);
        }
    }

    // Block-level loss aggregation (once per block, at the tail).
    __shared__ float s_loss[WPB];
    __shared__ bool  s_last;
    if (lane == 0) s_loss[warp] = lloss;
    __syncthreads();

    if (threadIdx.x == 0) {
        float t = 0.0f;
#pragma unroll
        for (int i = 0; i < WPB; i++) t += s_loss[i];
        unsigned long long q = (unsigned long long)(t * LOSS_SCALE + 0.5f);
        atomicAdd(&g_loss_acc, q);                      // relaxed REDG (proven free)
        // Arrival: release orders the REDG above; acquire (for the winner)
        // makes all released adds visible. Once per block, tail-positioned.
        unsigned int old;
        asm volatile("atom.global.add.acq_rel.gpu.u32 %0, [%1], %2;"
                     : "=r"(old) : "l"(&g_arrive), "r"(1u) : "memory");
        s_last = (old == (unsigned int)(GRID - 1));
    }
    __syncthreads();

    // Last-arriving block: publish loss, reset scratch for graph replay.
    if (s_last && threadIdx.x == 0) {
        unsigned long long total = atomicAdd(&g_loss_acc, 0ull);
        out[0] = (float)((double)total * (1.0 / ((double)LOSS_SCALE * (double)NB)));
        g_loss_acc = 0ull;
        g_arrive   = 0u;
    }
}

extern "C" void kernel_launch(void* const* d_in, const int* in_sizes, int n_in,
                              void* d_out, int out_size)
{
    // metadata order follows setup_inputs: input, factor, label, centers
    const float* input   = (const float*)d_in[0];
    const float* factor  = (const float*)d_in[1];
    const int*   label   = (const int*)d_in[2];
    const float* centers = (const float*)d_in[3];

    float* out = (float*)d_out;   // out[0]=loss, out[1..NB]=predict_a

    predict_persist<<<GRID, THREADS>>>(input, factor, label, centers, out);
}

// round 14
// speedup vs baseline: 1.0214x; 1.0214x over previous
#include <cuda_runtime.h>
#include <cstdint>

// Problem constants (fixed by the reference setup)
#define NB 65536        // batch rows
#define NF 512          // in_features
#define NK 1299         // number of centers
#define WARPS_PER_BLOCK 8
#define NBLOCKS (NB / WARPS_PER_BLOCK)   // 8192 hot blocks, 1 warp per row

// Fixed-point loss accumulator: integer adds commute exactly -> deterministic.
#define LOSS_SCALE 1073741824.0f   // 2^30
__device__ unsigned long long g_loss_acc;   // zero-init; waiter resets
__device__ unsigned int      g_arrive;      // zero-init; waiter resets

// Single launch: blocks 0..8191 = frozen streaming loop (unchanged);
// block 8192 = waiter that publishes the loss during the final-wave drain.
// Hot-block tail adds ONE no-return red.release (REDG-class, proven free).
__global__ __launch_bounds__(WARPS_PER_BLOCK * 32)
void predict_kernel(const float* __restrict__ input,
                    const float* __restrict__ factor,
                    const int* __restrict__ label,     // JAX downcasts int64->int32
                    const float* __restrict__ centers,
                    float* __restrict__ out)           // out[0]=loss, out[1..NB]=pred
{
    if (blockIdx.x == NBLOCKS) {
        // ---- Waiter block (scheduled last; overlaps the drain) ----
        if (threadIdx.x == 0) {
            unsigned int a;
            do {
                asm volatile("ld.acquire.gpu.global.u32 %0, [%1];"
                             : "=r"(a) : "l"(&g_arrive) : "memory");
            } while (a < (unsigned int)NBLOCKS);
            // Acquire above pairs with each hot block's red.release:
            // all 8192 loss REDGs are now visible.
            unsigned long long total;
            asm volatile("ld.acquire.gpu.global.u64 %0, [%1];"
                         : "=l"(total) : "l"(&g_loss_acc) : "memory");
            out[0] = (float)((double)total * (1.0 / ((double)LOSS_SCALE * (double)NB)));
            g_loss_acc = 0ull;                          // clean state for replay
            g_arrive   = 0u;
        }
        return;
    }

    // ---- Hot path: byte-equivalent to the frozen 24.7us round-7 loop ----
    const int warp = threadIdx.x >> 5;
    const int lane = threadIdx.x & 31;
    const int b = blockIdx.x * WARPS_PER_BLOCK + warp;

    const float4* in4 = reinterpret_cast<const float4*>(input + (size_t)b * NF);
    int c = label[b];
    c = (c < 0) ? 0 : (c >= NK ? NK - 1 : c);          // in-bounds insurance
    const float4* ce4 = reinterpret_cast<const float4*>(centers + (size_t)c * NF);

    // input: zero reuse -> bypass L1 (__ldcg), keep L1 capacity for centers.
    float acc = 0.0f;
#pragma unroll
    for (int i = 0; i < 4; i++) {
        float4 a = __ldcg(&in4[lane + 32 * i]);
        float4 w = ce4[lane + 32 * i];
        acc += a.x * w.x + a.y * w.y + a.z * w.z + a.w * w.w;
    }

#pragma unroll
    for (int o = 16; o; o >>= 1)
        acc += __shfl_xor_sync(0xffffffffu, acc, o);

    __shared__ float s_loss[WARPS_PER_BLOCK];
    if (lane == 0) {
        float p = 12.0f * tanhf(acc);
        __stcg(&out[1 + b], p);                        // streamed output, skip L1
        float d = p - factor[b];
        float ad = fabsf(d);
        s_loss[warp] = (ad < 1.0f) ? 0.5f * d * d : (ad - 0.5f);
    }
    __syncthreads();

    if (threadIdx.x == 0) {
        float t = 0.0f;
#pragma unroll
        for (int i = 0; i < WARPS_PER_BLOCK; i++) t += s_loss[i];
        unsigned long long q = (unsigned long long)(t * LOSS_SCALE + 0.5f);
        atomicAdd(&g_loss_acc, q);                     // no-return REDG (free)
        // Release-reduction arrival: orders the loss REDG above before the
        // tick becomes visible. No return value, no acquire, no L1 flush.
        asm volatile("red.release.gpu.global.add.u32 [%0], %1;"
                     :: "l"(&g_arrive), "r"(1u) : "memory");
    }
}

extern "C" void kernel_launch(void* const* d_in, const int* in_sizes, int n_in,
                              void* d_out, int out_size)
{
    // metadata order follows setup_inputs: input, factor, label, centers
    const float* input   = (const float*)d_in[0];
    const float* factor  = (const float*)d_in[1];
    const int*   label   = (const int*)d_in[2];
    const float* centers = (const float*)d_in[3];

    float* out = (float*)d_out;   // out[0]=loss, out[1..NB]=predict_a

    predict_kernel<<<NBLOCKS + 1, WARPS_PER_BLOCK * 32>>>(input, factor, label, centers, out);
}

// round 15
// speedup vs baseline: 1.0727x; 1.0502x over previous
#include <cuda_runtime.h>
#include <cstdint>

// Problem constants (fixed by the reference setup)
#define NB 65536        // batch rows
#define NF 512          // in_features
#define NK 1299         // number of centers
#define WARPS_PER_BLOCK 4
#define NBLOCKS (NB / WARPS_PER_BLOCK)   // 16384 blocks, 1 warp per row

// Fixed-point loss accumulator: integer adds commute exactly -> bit-deterministic
// regardless of block scheduling order. Partials >= 0, <= ~64; scale 2^30 =>
// max total ~2^50 < 2^63. atomicAdd return unused -> REDG (no-return), free.
#define LOSS_SCALE 1073741824.0f   // 2^30
__device__ unsigned long long g_loss_acc;   // zero-init; finisher resets it

// Kernel 1: per-row gathered dot product + tanh + smooth-L1 term.
// One warp per row: 512 floats = 128 float4 = 4 float4 per lane (MLP_p1=4,
// the proven-optimal per-warp load depth). Only change vs the 29.2us winner:
// 128-thread blocks (4 warps) to shrink per-block L1tex bunching + sync tail.
__global__ __launch_bounds__(WARPS_PER_BLOCK * 32)
void predict_kernel(const float* __restrict__ input,
                    const float* __restrict__ factor,
                    const int* __restrict__ label,     // JAX downcasts int64->int32
                    const float* __restrict__ centers,
                    float* __restrict__ pred_out)      // points at d_out+1
{
    const int warp = threadIdx.x >> 5;
    const int lane = threadIdx.x & 31;
    const int b = blockIdx.x * WARPS_PER_BLOCK + warp;

    const float4* in4 = reinterpret_cast<const float4*>(input + (size_t)b * NF);
    int c = label[b];
    c = (c < 0) ? 0 : (c >= NK ? NK - 1 : c);          // in-bounds insurance
    const float4* ce4 = reinterpret_cast<const float4*>(centers + (size_t)c * NF);

    // input: zero reuse -> bypass L1 (__ldcg), keep L1 capacity for centers.
    float acc = 0.0f;
#pragma unroll
    for (int i = 0; i < 4; i++) {
        float4 a = __ldcg(&in4[lane + 32 * i]);
        float4 w = ce4[lane + 32 * i];
        acc += a.x * w.x + a.y * w.y + a.z * w.z + a.w * w.w;
    }

#pragma unroll
    for (int o = 16; o; o >>= 1)
        acc += __shfl_xor_sync(0xffffffffu, acc, o);

    __shared__ float s_loss[WARPS_PER_BLOCK];
    if (lane == 0) {
        float p = 12.0f * tanhf(acc);
        __stcg(&pred_out[b], p);                       // streamed output, skip L1
        float d = p - factor[b];
        float ad = fabsf(d);
        s_loss[warp] = (ad < 1.0f) ? 0.5f * d * d : (ad - 0.5f);
    }
    __syncthreads();

    if (threadIdx.x == 0) {
        float t = 0.0f;
#pragma unroll
        for (int i = 0; i < WARPS_PER_BLOCK; i++) t += s_loss[i];
        unsigned long long q = (unsigned long long)(t * LOSS_SCALE + 0.5f);
        atomicAdd(&g_loss_acc, q);   // return unused -> REDG, no return trip
    }
}

// Kernel 2: trivial finisher — scale the fixed-point sum, reset accumulator.
__global__ void loss_finish_kernel(float* __restrict__ out)
{
    unsigned long long q = g_loss_acc;
    out[0] = (float)((double)q * (1.0 / ((double)LOSS_SCALE * (double)NB)));
    g_loss_acc = 0ull;                                 // clean state for next replay
}

extern "C" void kernel_launch(void* const* d_in, const int* in_sizes, int n_in,
                              void* d_out, int out_size)
{
    // metadata order follows setup_inputs: input, factor, label, centers
    const float* input   = (const float*)d_in[0];
    const float* factor  = (const float*)d_in[1];
    const int*   label   = (const int*)d_in[2];
    const float* centers = (const float*)d_in[3];

    float* out = (float*)d_out;   // out[0]=loss, out[1..NB]=predict_a
    float* pred_out = out + 1;

    predict_kernel<<<NBLOCKS, WARPS_PER_BLOCK * 32>>>(input, factor, label, centers, pred_out);
    loss_finish_kernel<<<1, 1>>>(out);
}

// round 16
// speedup vs baseline: 1.2257x; 1.1427x over previous
#include <cuda_runtime.h>
#include <cstdint>

// Problem constants (fixed by the reference setup)
#define NB 65536        // batch rows
#define NF 512          // in_features
#define NK 1299         // number of centers
#define WARPS_PER_BLOCK 8
#define NBLOCKS (NB / WARPS_PER_BLOCK)   // 8192 blocks, 1 warp per row

// Fixed-point loss accumulator: integer adds commute exactly -> bit-deterministic
// regardless of block scheduling order. Partials >= 0, <= ~128; scale 2^30 =>
// max total ~2^50 < 2^63. atomicAdd return unused -> REDG (no-return), free.
#define LOSS_SCALE 1073741824.0f   // 2^30
__device__ unsigned long long g_loss_acc;   // zero-init; finisher resets it

// Kernel 1: per-row gathered dot product + tanh + smooth-L1 term.
// One warp per row, 256-thread blocks (proven optimal: 24.7us).
// Sole change vs the 29.2us champion: input via __ldcs (evict-first in L2)
// so the 128MB one-pass stream cannot evict the 2.6MB centers table from L2.
__global__ __launch_bounds__(WARPS_PER_BLOCK * 32)
void predict_kernel(const float* __restrict__ input,
                    const float* __restrict__ factor,
                    const int* __restrict__ label,     // JAX downcasts int64->int32
                    const float* __restrict__ centers,
                    float* __restrict__ pred_out)      // points at d_out+1
{
    const int warp = threadIdx.x >> 5;
    const int lane = threadIdx.x & 31;
    const int b = blockIdx.x * WARPS_PER_BLOCK + warp;

    const float4* in4 = reinterpret_cast<const float4*>(input + (size_t)b * NF);
    int c = label[b];
    c = (c < 0) ? 0 : (c >= NK ? NK - 1 : c);          // in-bounds insurance
    const float4* ce4 = reinterpret_cast<const float4*>(centers + (size_t)c * NF);

    // input: one-pass stream -> evict-first (L1-bypass + L2 streaming policy);
    // centers: default caching (L1 + L2-resident).
    float acc = 0.0f;
#pragma unroll
    for (int i = 0; i < 4; i++) {
        float4 a = __ldcs(&in4[lane + 32 * i]);
        float4 w = ce4[lane + 32 * i];
        acc += a.x * w.x + a.y * w.y + a.z * w.z + a.w * w.w;
    }

#pragma unroll
    for (int o = 16; o; o >>= 1)
        acc += __shfl_xor_sync(0xffffffffu, acc, o);

    __shared__ float s_loss[WARPS_PER_BLOCK];
    if (lane == 0) {
        float p = 12.0f * tanhf(acc);
        __stcg(&pred_out[b], p);                       // streamed output, skip L1
        float d = p - factor[b];
        float ad = fabsf(d);
        s_loss[warp] = (ad < 1.0f) ? 0.5f * d * d : (ad - 0.5f);
    }
    __syncthreads();

    if (threadIdx.x == 0) {
        float t = 0.0f;
#pragma unroll
        for (int i = 0; i < WARPS_PER_BLOCK; i++) t += s_loss[i];
        unsigned long long q = (unsigned long long)(t * LOSS_SCALE + 0.5f);
        atomicAdd(&g_loss_acc, q);   // return unused -> REDG, no return trip
    }
}

// Kernel 2: trivial finisher — scale the fixed-point sum, reset accumulator.
__global__ void loss_finish_kernel(float* __restrict__ out)
{
    unsigned long long q = g_loss_acc;
    out[0] = (float)((double)q * (1.0 / ((double)LOSS_SCALE * (double)NB)));
    g_loss_acc = 0ull;                                 // clean state for next replay
}

extern "C" void kernel_launch(void* const* d_in, const int* in_sizes, int n_in,
                              void* d_out, int out_size)
{
    // metadata order follows setup_inputs: input, factor, label, centers
    const float* input   = (const float*)d_in[0];
    const float* factor  = (const float*)d_in[1];
    const int*   label   = (const int*)d_in[2];
    const float* centers = (const float*)d_in[3];

    float* out = (float*)d_out;   // out[0]=loss, out[1..NB]=predict_a
    float* pred_out = out + 1;

    predict_kernel<<<NBLOCKS, WARPS_PER_BLOCK * 32>>>(input, factor, label, centers, pred_out);
    loss_finish_kernel<<<1, 1>>>(out);
}